// round 5
// baseline (speedup 1.0000x reference)
#include <cuda_runtime.h>

// YOLOLoss fused, round 5.
// - 672 of 704 blocks are pure dense: load conf -> softplus -> reduce -> 1 smem atomic.
// - Target work (tg load, dedup, positives, ignore-subtract) only in blockIdx.x==0.
// - Partials fan out to g_part[32][8] (max 22 ops/address); two-level counters.

#define BSZ     32
#define NT      50
#define HH      104
#define WW      104
#define HW      (HH*WW)                 // 10816
#define NCLS    20
#define BLK_POS 512                     // 256 thr x 2 positions
#define NBX     ((HW + BLK_POS - 1) / BLK_POS)   // 22
#define NCELL   ((double)(BSZ * 3 * HW))

__device__ double   g_part[BSZ][8];     // zero-init; reset by finalizer
__device__ unsigned g_bctr[BSZ];        // per-batch block counters
__device__ unsigned g_fctr;             // batch-done counter

// min(softplus(z), 100) == -clip(log(1 - sigmoid(z)), -100); spl(-z) for -log(p)
__device__ __forceinline__ float spl(float z) {
    return fminf(__logf(1.0f + __expf(z)), 100.0f);
}

__global__ __launch_bounds__(256)
void yolo_fused(const float* __restrict__ in, const float* __restrict__ tg,
                float* __restrict__ out)
{
    __shared__ float  s_acc[8];         // sx, sy, sw, sh, scf, sno, scl, np
    __shared__ int    s_meta[NT];
    __shared__ int    s_last;
    __shared__ double s_tot[8];

    const int b    = blockIdx.y;
    const int tid  = threadIdx.x;
    const int P0   = blockIdx.x * BLK_POS;
    const int lane = tid & 31, wrp = tid >> 5;
    const bool tgt_blk = (blockIdx.x == 0);

    // ---- dense conf loads first (2 positions x 3 anchors) ----
    const int  p0   = P0 + tid * 2;
    const bool live = (p0 < HW);
    const float* base = in + (size_t)b * 75 * HW;
    float2 c0, c1, c2;
    if (live) {
        c0 = *(const float2*)(base + (size_t)( 4) * HW + p0);
        c1 = *(const float2*)(base + (size_t)(29) * HW + p0);
        c2 = *(const float2*)(base + (size_t)(54) * HW + p0);
    }
    if (tid < 8) s_acc[tid] = 0.0f;

    // ---- target prologue: ONLY block x==0 of each batch ----
    int   mymeta = 0x7FFFFFFF;          // invalid sentinel
    float mytx = 0.f, myty = 0.f, mytw = 0.f, myth = 0.f;
    if (tgt_blk && tid < NT) {
        const float* t = tg + ((size_t)b * NT + tid) * 5;
        float t0 = t[0], t1 = t[1], t2 = t[2], t3 = t[3], t4 = t[4];
        if (t0 + t1 + t2 + t3 + t4 > 0.0f) {
            float gx = t0 * (float)WW, gy = t1 * (float)HH;
            float gw = t2 * (float)WW, gh = t3 * (float)HH;
            int gi = (int)gx, gj = (int)gy;
            const float aw[3] = {14.5f, 19.5f, 46.625f};   // ANCHORS / 8
            const float ah[3] = {11.25f, 24.75f, 40.75f};
            float area = (gw + 1.0f) * (gh + 1.0f);
            float best = -1.0f; int bn = 0, nz = 0;
            #pragma unroll
            for (int a = 0; a < 3; a++) {
                float inter = fmaxf(fminf(gw, aw[a]) + 1.0f, 0.0f) *
                              fmaxf(fminf(gh, ah[a]) + 1.0f, 0.0f);
                float iou = inter / (area + (aw[a] + 1.0f) * (ah[a] + 1.0f) - inter + 1e-16f);
                if (iou > best) { best = iou; bn = a; }      // first max wins
                if (iou > 0.5f) nz |= (1 << a);
            }
            mytx = gx - (float)gi;
            myty = gy - (float)gj;
            mytw = __logf(gw / aw[bn] + 1e-16f);
            myth = __logf(gh / ah[bn] + 1e-16f);
            mymeta = (gj * WW + gi) | (bn << 14) | (nz << 16) | (((int)t4) << 19);
        }
        s_meta[tid] = mymeta;
    }

    // ---- speculative loads for valid targets (pre-barrier) ----
    const bool valid = tgt_blk && (mymeta != 0x7FFFFFFF);
    float vx = 0, vy = 0, vw = 0, vh = 0, vc = 0, cfa0 = 0, cfa1 = 0, cfa2 = 0;
    int   mypos = 0, mya = 0;
    if (valid) {
        mypos = mymeta & 0x3FFF;
        mya   = (mymeta >> 14) & 3;
        const float* ch = base + (size_t)(mya * 25) * HW + mypos;
        vx = ch[0]; vy = ch[HW]; vw = ch[2 * HW]; vh = ch[3 * HW]; vc = ch[4 * HW];
        cfa0 = base[(size_t)( 4) * HW + mypos];
        cfa1 = base[(size_t)(29) * HW + mypos];
        cfa2 = base[(size_t)(54) * HW + mypos];
    }

    // ---- dense math (target-independent: no mask) ----
    float a_no = 0.0f;
    if (live)
        a_no = spl(c0.x) + spl(c0.y) + spl(c1.x) + spl(c1.y) + spl(c2.x) + spl(c2.y);
    #pragma unroll
    for (int off = 16; off > 0; off >>= 1)
        a_no += __shfl_down_sync(0xFFFFFFFFu, a_no, off);

    __syncthreads();                    // s_acc zero + s_meta ready
    if (lane == 0 && a_no != 0.0f) atomicAdd(&s_acc[5], a_no);

    // ---- target resolution (one block per batch) ----
    if (valid) {
        int      mynz  = (mymeta >> 16) & 7;
        unsigned cm    = 1u << ((mymeta >> 19) & 31);
        bool     alive = true;
        int      subnz = mynz;
        for (int u = 0; u < NT; u++) {
            if (u == tid) continue;
            int mu = s_meta[u];
            if ((mu & 0x3FFF) != mypos) continue;            // sentinel never matches
            if (((mu >> 14) & 3) == mya) {
                if (u > tid) alive = false;                  // last duplicate wins
                else         cm |= 1u << ((mu >> 19) & 31);  // union earlier classes
            }
            if (u < tid) subnz &= ~((mu >> 16) & 7);         // dedup ignore ownership
        }
        float sub = 0.0f;               // remove ignored cells from dense sum
        if (subnz & 1) sub += spl(cfa0);
        if (subnz & 2) sub += spl(cfa1);
        if (subnz & 4) sub += spl(cfa2);
        if (sub != 0.0f) atomicAdd(&s_acc[5], -sub);

        if (alive) {
            const float* ch = base + (size_t)(mya * 25) * HW + mypos;
            float pc[NCLS];
            #pragma unroll
            for (int c = 0; c < NCLS; c++) pc[c] = ch[(size_t)(5 + c) * HW];
            float scl = 0.0f;
            #pragma unroll
            for (int c = 0; c < NCLS; c++)
                scl += spl(((cm >> c) & 1) ? -pc[c] : pc[c]);
            // BCE(sigm(z), t) = t*spl(-z) + (1-t)*spl(z)
            atomicAdd(&s_acc[0], mytx * spl(-vx) + (1.0f - mytx) * spl(vx));
            atomicAdd(&s_acc[1], myty * spl(-vy) + (1.0f - myty) * spl(vy));
            float dw = vw - mytw, dh = vh - myth;
            atomicAdd(&s_acc[2], dw * dw);
            atomicAdd(&s_acc[3], dh * dh);
            atomicAdd(&s_acc[4], spl(-vc));
            atomicAdd(&s_acc[6], scl);
            atomicAdd(&s_acc[7], 1.0f);
        }
    }
    __syncthreads();

    // ---- block partial -> per-batch slot (max 22 ops per address) ----
    if (tid < 8) {
        float v = s_acc[tid];
        if (v != 0.0f) atomicAdd(&g_part[b][tid], (double)v);
    }
    __threadfence();
    __syncthreads();

    // ---- two-level completion counters ----
    if (tid == 0) {
        int done = 0;
        if (atomicAdd(&g_bctr[b], 1u) == NBX - 1) {          // last block of batch b
            __threadfence();
            if (atomicAdd(&g_fctr, 1u) == BSZ - 1) done = 1; // last batch overall
        }
        s_last = done;
    }
    __syncthreads();

    // ---- finalize: gather 32x8 partials, write 6 outputs, reset state ----
    if (s_last) {
        __threadfence();
        double v = atomicAdd(&g_part[lane][wrp], 0.0);       // coherent read (old value)
        #pragma unroll
        for (int off = 16; off > 0; off >>= 1)
            v += __shfl_down_sync(0xFFFFFFFFu, v, off);
        if (lane == 0) s_tot[wrp] = v;
        g_part[lane][wrp] = 0.0;                             // reset own cell
        if (tid < BSZ) g_bctr[tid] = 0;
        __syncthreads();
        if (tid == 0) {
            g_fctr = 0;
            double sx = s_tot[0], sy = s_tot[1], sw = s_tot[2], sh = s_tot[3];
            double scf = s_tot[4], sno = s_tot[5], scl = s_tot[6], np = s_tot[7];
            out[0] = (float)(2.5 * sx / NCELL);
            out[1] = (float)(2.5 * sy / NCELL);
            out[2] = (float)(2.5 * sw / NCELL);
            out[3] = (float)(2.5 * sh / NCELL);
            out[4] = (float)((scf + 0.5 * sno) / NCELL);
            out[5] = (float)(scl / fmax(np * 20.0, 1.0));
        }
    }
}

extern "C" void kernel_launch(void* const* d_in, const int* in_sizes, int n_in,
                              void* d_out, int out_size) {
    const float* in = (const float*)d_in[0];   // (32,75,104,104)
    const float* tg = (const float*)d_in[1];   // (32,50,5)
    float* out = (float*)d_out;                // 6 floats

    dim3 grid(NBX, BSZ);                       // (22, 32) = 704 blocks
    yolo_fused<<<grid, 256>>>(in, tg, out);
}

// round 6
// speedup vs baseline: 1.0804x; 1.0804x over previous
#include <cuda_runtime.h>

// YOLOLoss fused, round 6: single-wave design.
// 148 blocks x 256 threads (one block per SM). Each thread: 7 coalesced float4
// quads of conf data (grid-strided). Targets handled by blocks 0..31 (batch =
// blockIdx.x), overlapping the dense loads. One tail per SM.

#define BSZ     32
#define NT      50
#define HH      104
#define WW      104
#define HW      (HH*WW)                 // 10816
#define NCLS    20
#define NBLK    148                     // one wave on GB300 (148+ SMs)
#define NTHR    256
#define QPC     (HW/4)                  // 2704 quads per channel-row
#define NROW    (BSZ*3)                 // 96 conf channel-rows
#define TOTQ    (NROW*QPC)              // 259584 quads
#define GRIDQ   (NBLK*NTHR)             // 37888
#define KQ      7                       // ceil(TOTQ/GRIDQ)
#define NCELL   ((double)(BSZ * 3 * HW))

__device__ double   g_acc[8];           // zero-init; reset by finalizer
__device__ unsigned g_ctr;

// min(softplus(z), 100) == -clip(log(1-sigmoid(z)), -100); spl(-z) == -clip(log(sigmoid(z)), -100)
__device__ __forceinline__ float spl(float z) {
    return fminf(__logf(1.0f + __expf(z)), 100.0f);
}

__global__ __launch_bounds__(NTHR)
void yolo_fused(const float* __restrict__ in, const float* __restrict__ tg,
                float* __restrict__ out)
{
    __shared__ float s_acc[8];          // sx, sy, sw, sh, scf, sno, scl, np
    __shared__ int   s_meta[NT];
    __shared__ int   s_last;

    const int tid  = threadIdx.x;
    const int bx   = blockIdx.x;
    const int lane = tid & 31;
    const int b    = bx;                // batch for target blocks (bx < 32)

    // ---- 1. issue all dense conf loads (coalesced, MLP=7) ----
    const int Qbase = bx * NTHR + tid;
    float4 v[KQ];
    #pragma unroll
    for (int k = 0; k < KQ; k++) {
        int Q = Qbase + k * GRIDQ;
        if (Q < TOTQ) {
            int r = Q / QPC;            // channel-row: 25*r+4 is the conf channel
            int o = Q - r * QPC;
            v[k] = *(const float4*)(in + (size_t)(25 * r + 4) * HW + 4 * o);
        }
    }
    if (tid < 8) s_acc[tid] = 0.0f;

    // ---- 2. target prologue (blocks 0..31 only, threads 0..49) ----
    int   mymeta = 0x7FFFFFFF;
    float mytx = 0.f, myty = 0.f, mytw = 0.f, myth = 0.f;
    if (bx < BSZ && tid < NT) {
        const float* t = tg + ((size_t)b * NT + tid) * 5;
        float t0 = t[0], t1 = t[1], t2 = t[2], t3 = t[3], t4 = t[4];
        if (t0 + t1 + t2 + t3 + t4 > 0.0f) {
            float gx = t0 * (float)WW, gy = t1 * (float)HH;
            float gw = t2 * (float)WW, gh = t3 * (float)HH;
            int gi = (int)gx, gj = (int)gy;
            const float aw[3] = {14.5f, 19.5f, 46.625f};   // ANCHORS / 8
            const float ah[3] = {11.25f, 24.75f, 40.75f};
            float area = (gw + 1.0f) * (gh + 1.0f);
            float best = -1.0f; int bn = 0, nz = 0;
            #pragma unroll
            for (int a = 0; a < 3; a++) {
                float inter = fmaxf(fminf(gw, aw[a]) + 1.0f, 0.0f) *
                              fmaxf(fminf(gh, ah[a]) + 1.0f, 0.0f);
                float iou = inter / (area + (aw[a] + 1.0f) * (ah[a] + 1.0f) - inter + 1e-16f);
                if (iou > best) { best = iou; bn = a; }      // first max wins
                if (iou > 0.5f) nz |= (1 << a);
            }
            mytx = gx - (float)gi;
            myty = gy - (float)gj;
            mytw = __logf(gw / aw[bn] + 1e-16f);
            myth = __logf(gh / ah[bn] + 1e-16f);
            mymeta = (gj * WW + gi) | (bn << 14) | (nz << 16) | (((int)t4) << 19);
        }
        s_meta[tid] = mymeta;
    }

    // ---- 3. speculative positive-cell loads (own meta only, pre-barrier) ----
    const bool valid = (bx < BSZ) && (mymeta != 0x7FFFFFFF);
    const float* base = in + (size_t)b * 75 * HW;
    float vx = 0, vy = 0, vw = 0, vh = 0, vc = 0, cfa0 = 0, cfa1 = 0, cfa2 = 0;
    int   mypos = 0, mya = 0;
    if (valid) {
        mypos = mymeta & 0x3FFF;
        mya   = (mymeta >> 14) & 3;
        const float* ch = base + (size_t)(mya * 25) * HW + mypos;
        vx = ch[0]; vy = ch[HW]; vw = ch[2 * HW]; vh = ch[3 * HW]; vc = ch[4 * HW];
        cfa0 = base[(size_t)( 4) * HW + mypos];
        cfa1 = base[(size_t)(29) * HW + mypos];
        cfa2 = base[(size_t)(54) * HW + mypos];
    }

    // ---- 4. dense math (target-independent; unconditional softplus sum) ----
    float a_no = 0.0f;
    #pragma unroll
    for (int k = 0; k < KQ; k++) {
        int Q = Qbase + k * GRIDQ;
        if (Q < TOTQ)
            a_no += spl(v[k].x) + spl(v[k].y) + spl(v[k].z) + spl(v[k].w);
    }
    #pragma unroll
    for (int off = 16; off > 0; off >>= 1)
        a_no += __shfl_down_sync(0xFFFFFFFFu, a_no, off);

    __syncthreads();                    // s_acc zeroed, s_meta published
    if (lane == 0) atomicAdd(&s_acc[5], a_no);

    // ---- 5. target resolution (dedup, ignore-subtract, positives) ----
    if (valid) {
        int      mynz  = (mymeta >> 16) & 7;
        unsigned cm    = 1u << ((mymeta >> 19) & 31);
        bool     alive = true;
        int      subnz = mynz;
        for (int u = 0; u < NT; u++) {
            if (u == tid) continue;
            int mu = s_meta[u];
            if ((mu & 0x3FFF) != mypos) continue;            // sentinel never matches
            if (((mu >> 14) & 3) == mya) {
                if (u > tid) alive = false;                  // last duplicate wins
                else         cm |= 1u << ((mu >> 19) & 31);  // union earlier classes
            }
            if (u < tid) subnz &= ~((mu >> 16) & 7);         // dedup ignore ownership
        }
        float sub = 0.0f;               // remove ignored cells from dense sum
        if (subnz & 1) sub += spl(cfa0);
        if (subnz & 2) sub += spl(cfa1);
        if (subnz & 4) sub += spl(cfa2);
        if (sub != 0.0f) atomicAdd(&s_acc[5], -sub);

        if (alive) {
            const float* ch = base + (size_t)(mya * 25) * HW + mypos;
            float pc[NCLS];
            #pragma unroll
            for (int c = 0; c < NCLS; c++) pc[c] = ch[(size_t)(5 + c) * HW];
            float scl = 0.0f;
            #pragma unroll
            for (int c = 0; c < NCLS; c++)
                scl += spl(((cm >> c) & 1) ? -pc[c] : pc[c]);
            // BCE(sigm(z), t) = t*spl(-z) + (1-t)*spl(z)
            atomicAdd(&s_acc[0], mytx * spl(-vx) + (1.0f - mytx) * spl(vx));
            atomicAdd(&s_acc[1], myty * spl(-vy) + (1.0f - myty) * spl(vy));
            float dw = vw - mytw, dh = vh - myth;
            atomicAdd(&s_acc[2], dw * dw);
            atomicAdd(&s_acc[3], dh * dh);
            atomicAdd(&s_acc[4], spl(-vc));
            atomicAdd(&s_acc[6], scl);
            atomicAdd(&s_acc[7], 1.0f);
        }
    }
    __syncthreads();

    // ---- 6. one global accumulation per block (148 ops / address) ----
    if (tid < 8) {
        float p = s_acc[tid];
        if (p != 0.0f) atomicAdd(&g_acc[tid], (double)p);
    }
    __threadfence();
    __syncthreads();
    if (tid == 0) s_last = (atomicAdd(&g_ctr, 1) == NBLK - 1);
    __syncthreads();

    // ---- 7. last block finalizes + resets persistent state ----
    if (s_last && tid == 0) {
        __threadfence();
        double A[8];
        #pragma unroll
        for (int i = 0; i < 8; i++) A[i] = atomicAdd(&g_acc[i], 0.0);  // coherent read
        out[0] = (float)(2.5 * A[0] / NCELL);
        out[1] = (float)(2.5 * A[1] / NCELL);
        out[2] = (float)(2.5 * A[2] / NCELL);
        out[3] = (float)(2.5 * A[3] / NCELL);
        out[4] = (float)((A[4] + 0.5 * A[5]) / NCELL);
        out[5] = (float)(A[6] / fmax(A[7] * 20.0, 1.0));
        #pragma unroll
        for (int i = 0; i < 8; i++) g_acc[i] = 0.0;          // reset for next replay
        __threadfence();
        g_ctr = 0;
    }
}

extern "C" void kernel_launch(void* const* d_in, const int* in_sizes, int n_in,
                              void* d_out, int out_size) {
    const float* in = (const float*)d_in[0];   // (32,75,104,104)
    const float* tg = (const float*)d_in[1];   // (32,50,5)
    float* out = (float*)d_out;                // 6 floats

    yolo_fused<<<NBLK, NTHR>>>(in, tg, out);   // 148 blocks = one wave
}

// round 7
// speedup vs baseline: 1.2329x; 1.1412x over previous
#include <cuda_runtime.h>

// YOLOLoss fused, round 7: occupancy-first design.
// 1024 identical blocks (32 x-blocks x 32 batches) x 256 threads.
// Each thread: ONE float4 conf load + 4 softplus. Targets: block bx owns
// targets t with t%32==bx (<=2/block). Atomics fanned out per-batch.

#define BSZ     32
#define NT      50
#define HH      104
#define WW      104
#define HW      (HH*WW)                 // 10816
#define NCLS    20
#define QPC     (HW/4)                  // 2704 quads per conf channel
#define TPB     (3*QPC)                 // 8112 quad-tasks per batch
#define NXB     32                      // x-blocks per batch
#define NBLK    (NXB*BSZ)               // 1024
#define NCELL   ((double)(BSZ * 3 * HW))

__device__ double   g_part[BSZ][8];     // zero-init; reset by finalizer
__device__ unsigned g_bctr[BSZ];        // per-batch completion
__device__ unsigned g_fctr;             // overall completion

// min(softplus(z), 100) == -clip(log(1-sigmoid(z)), -100); spl(-z) == -clip(log(sigmoid(z)), -100)
__device__ __forceinline__ float spl(float z) {
    return fminf(__logf(1.0f + __expf(z)), 100.0f);
}

__global__ __launch_bounds__(256)
void yolo_fused(const float* __restrict__ in, const float* __restrict__ tg,
                float* __restrict__ out)
{
    __shared__ float  s_acc[8];         // sx, sy, sw, sh, scf, sno, scl, np
    __shared__ int    s_meta[NT];
    __shared__ int    s_last;
    __shared__ double s_tot[8];

    const int tid  = threadIdx.x;
    const int bx   = blockIdx.x;        // 0..31 within batch
    const int b    = blockIdx.y;        // batch
    const int lane = tid & 31, wrp = tid >> 5;

    // ---- 1. dense conf load: one float4 per thread, coalesced ----
    const int task = bx * 256 + tid;    // < TPB for all but tail of bx==31
    const bool live = (task < TPB);
    const float* base = in + (size_t)b * 75 * HW;
    float4 v;
    if (live) {
        int a = task / QPC;             // anchor 0..2 (const-div -> mul/shift)
        int q = task - a * QPC;
        v = *(const float4*)(base + (size_t)(a * 25 + 4) * HW + 4 * q);
    }
    if (tid < 8) s_acc[tid] = 0.0f;

    // ---- 2. target prologue (threads 0..49, every block) ----
    int   mymeta = 0x7FFFFFFF;
    float mytx = 0.f, myty = 0.f, mytw = 0.f, myth = 0.f;
    if (tid < NT) {
        const float* t = tg + ((size_t)b * NT + tid) * 5;
        float t0 = t[0], t1 = t[1], t2 = t[2], t3 = t[3], t4 = t[4];
        if (t0 + t1 + t2 + t3 + t4 > 0.0f) {
            float gx = t0 * (float)WW, gy = t1 * (float)HH;
            float gw = t2 * (float)WW, gh = t3 * (float)HH;
            int gi = (int)gx, gj = (int)gy;
            const float aw[3] = {14.5f, 19.5f, 46.625f};   // ANCHORS / 8
            const float ah[3] = {11.25f, 24.75f, 40.75f};
            float area = (gw + 1.0f) * (gh + 1.0f);
            float best = -1.0f; int bn = 0, nz = 0;
            #pragma unroll
            for (int a = 0; a < 3; a++) {
                float inter = fmaxf(fminf(gw, aw[a]) + 1.0f, 0.0f) *
                              fmaxf(fminf(gh, ah[a]) + 1.0f, 0.0f);
                float iou = inter / (area + (aw[a] + 1.0f) * (ah[a] + 1.0f) - inter + 1e-16f);
                if (iou > best) { best = iou; bn = a; }      // first max wins
                if (iou > 0.5f) nz |= (1 << a);
            }
            mytx = gx - (float)gi;
            myty = gy - (float)gj;
            mytw = __logf(gw / aw[bn] + 1e-16f);
            myth = __logf(gh / ah[bn] + 1e-16f);
            mymeta = (gj * WW + gi) | (bn << 14) | (nz << 16) | (((int)t4) << 19);
        }
        s_meta[tid] = mymeta;
    }

    // ---- 3. ownership (t%32 == bx) + speculative loads pre-barrier ----
    const bool owner = (tid < NT) && ((tid & 31) == bx) && (mymeta != 0x7FFFFFFF);
    float vx = 0, vy = 0, vw = 0, vh = 0, vc = 0, cfa0 = 0, cfa1 = 0, cfa2 = 0;
    int   mypos = 0, mya = 0;
    if (owner) {
        mypos = mymeta & 0x3FFF;
        mya   = (mymeta >> 14) & 3;
        const float* ch = base + (size_t)(mya * 25) * HW + mypos;
        vx = ch[0]; vy = ch[HW]; vw = ch[2 * HW]; vh = ch[3 * HW]; vc = ch[4 * HW];
        cfa0 = base[(size_t)( 4) * HW + mypos];
        cfa1 = base[(size_t)(29) * HW + mypos];
        cfa2 = base[(size_t)(54) * HW + mypos];
    }

    // ---- 4. dense math: unconditional softplus sum (no mask) ----
    float a_no = 0.0f;
    if (live)
        a_no = spl(v.x) + spl(v.y) + spl(v.z) + spl(v.w);
    #pragma unroll
    for (int off = 16; off > 0; off >>= 1)
        a_no += __shfl_down_sync(0xFFFFFFFFu, a_no, off);

    __syncthreads();                    // s_acc zeroed, s_meta published
    if (lane == 0) atomicAdd(&s_acc[5], a_no);

    // ---- 5. owner resolution: dedup, ignore-subtract, positive losses ----
    if (owner) {
        int      mynz  = (mymeta >> 16) & 7;
        unsigned cm    = 1u << ((mymeta >> 19) & 31);
        bool     alive = true;
        int      subnz = mynz;
        for (int u = 0; u < NT; u++) {
            if (u == tid) continue;
            int mu = s_meta[u];
            if ((mu & 0x3FFF) != mypos) continue;            // sentinel never matches
            if (((mu >> 14) & 3) == mya) {
                if (u > tid) alive = false;                  // last duplicate wins
                else         cm |= 1u << ((mu >> 19) & 31);  // union earlier classes
            }
            if (u < tid) subnz &= ~((mu >> 16) & 7);         // earliest owner subtracts
        }
        float sub = 0.0f;               // remove ignored cells from dense sum
        if (subnz & 1) sub += spl(cfa0);
        if (subnz & 2) sub += spl(cfa1);
        if (subnz & 4) sub += spl(cfa2);
        if (sub != 0.0f) atomicAdd(&s_acc[5], -sub);

        if (alive) {
            const float* ch = base + (size_t)(mya * 25) * HW + mypos;
            float pc[NCLS];
            #pragma unroll
            for (int c = 0; c < NCLS; c++) pc[c] = ch[(size_t)(5 + c) * HW];
            float scl = 0.0f;
            #pragma unroll
            for (int c = 0; c < NCLS; c++)
                scl += spl(((cm >> c) & 1) ? -pc[c] : pc[c]);
            // BCE(sigm(z), t) = t*spl(-z) + (1-t)*spl(z)
            atomicAdd(&s_acc[0], mytx * spl(-vx) + (1.0f - mytx) * spl(vx));
            atomicAdd(&s_acc[1], myty * spl(-vy) + (1.0f - myty) * spl(vy));
            float dw = vw - mytw, dh = vh - myth;
            atomicAdd(&s_acc[2], dw * dw);
            atomicAdd(&s_acc[3], dh * dh);
            atomicAdd(&s_acc[4], spl(-vc));
            atomicAdd(&s_acc[6], scl);
            atomicAdd(&s_acc[7], 1.0f);
        }
    }
    __syncthreads();

    // ---- 6. block partial -> per-batch slot (<=32 ops/address) ----
    if (tid < 8) {
        float p = s_acc[tid];
        if (p != 0.0f) atomicAdd(&g_part[b][tid], (double)p);
    }
    __threadfence();
    __syncthreads();

    // ---- 7. two-level completion ----
    if (tid == 0) {
        int done = 0;
        if (atomicAdd(&g_bctr[b], 1u) == NXB - 1) {          // last block of batch
            __threadfence();
            if (atomicAdd(&g_fctr, 1u) == BSZ - 1) done = 1; // last batch
        }
        s_last = done;
    }
    __syncthreads();

    // ---- 8. finalize: warp w reduces accumulator w across 32 batches ----
    if (s_last) {
        __threadfence();
        if (wrp < 8) {
            double vv = atomicAdd(&g_part[lane][wrp], 0.0);  // coherent read
            #pragma unroll
            for (int off = 16; off > 0; off >>= 1)
                vv += __shfl_down_sync(0xFFFFFFFFu, vv, off);
            if (lane == 0) s_tot[wrp] = vv;
            g_part[lane][wrp] = 0.0;                         // reset
        }
        if (tid < BSZ) g_bctr[tid] = 0;
        __syncthreads();
        if (tid == 0) {
            double sx = s_tot[0], sy = s_tot[1], sw = s_tot[2], sh = s_tot[3];
            double scf = s_tot[4], sno = s_tot[5], scl = s_tot[6], np = s_tot[7];
            out[0] = (float)(2.5 * sx / NCELL);
            out[1] = (float)(2.5 * sy / NCELL);
            out[2] = (float)(2.5 * sw / NCELL);
            out[3] = (float)(2.5 * sh / NCELL);
            out[4] = (float)((scf + 0.5 * sno) / NCELL);
            out[5] = (float)(scl / fmax(np * 20.0, 1.0));
            g_fctr = 0;
        }
    }
}

extern "C" void kernel_launch(void* const* d_in, const int* in_sizes, int n_in,
                              void* d_out, int out_size) {
    const float* in = (const float*)d_in[0];   // (32,75,104,104)
    const float* tg = (const float*)d_in[1];   // (32,50,5)
    float* out = (float*)d_out;                // 6 floats

    dim3 grid(NXB, BSZ);                       // (32, 32) = 1024 blocks
    yolo_fused<<<grid, 256>>>(in, tg, out);
}

// round 8
// speedup vs baseline: 1.4654x; 1.1886x over previous
#include <cuda_runtime.h>

// YOLOLoss fused, round 8: R4 structure with surgical cuts.
// - No mid-block full barrier: warps 0-1 sync via named barrier for target work;
//   warps 2-7 run pure dense (load -> softplus -> per-warp smem slot -> final sync).
// - Class-channel loads issued speculatively pre-barrier (one DRAM epoch, not two).
// - Sparse terms -> s_sparse (atomic, <=50 threads); dense -> s_no[warp] plain store.

#define BSZ     32
#define NT      50
#define HH      104
#define WW      104
#define HW      (HH*WW)                 // 10816
#define NCLS    20
#define BLK_POS 512                     // 256 thr x 2 positions
#define NBX     ((HW + BLK_POS - 1) / BLK_POS)   // 22
#define NBLK    (NBX * BSZ)             // 704
#define NCELL   ((double)(BSZ * 3 * HW))

__device__ double   g_acc[8];           // zero-init; reset by finalizer
__device__ unsigned g_ctr;

// min(softplus(z), 100) == -clip(log(1-sigmoid(z)), -100); spl(-z) == -clip(log(sigmoid(z)), -100)
__device__ __forceinline__ float spl(float z) {
    return fminf(__logf(1.0f + __expf(z)), 100.0f);
}

__global__ __launch_bounds__(256, 4)
void yolo_fused(const float* __restrict__ in, const float* __restrict__ tg,
                float* __restrict__ out)
{
    __shared__ float s_sparse[8];       // sx, sy, sw, sh, scf, [unused], scl, np
    __shared__ float s_no[8];           // per-warp dense partials (plain stores)
    __shared__ int   s_meta[NT];
    __shared__ int   s_last;

    const int tid  = threadIdx.x;
    const int b    = blockIdx.y;
    const int P0   = blockIdx.x * BLK_POS;
    const int lane = tid & 31, wrp = tid >> 5;

    // ---- 1. dense conf loads first (2 positions x 3 anchors, MLP=3) ----
    const int  p0   = P0 + tid * 2;
    const bool live = (p0 < HW);
    const float* base = in + (size_t)b * 75 * HW;
    float2 c0, c1, c2;
    if (live) {
        c0 = *(const float2*)(base + (size_t)( 4) * HW + p0);
        c1 = *(const float2*)(base + (size_t)(29) * HW + p0);
        c2 = *(const float2*)(base + (size_t)(54) * HW + p0);
    }

    // ---- 2. target path: warps 0-1 only ----
    if (tid < 64) {
        if (tid < 8) s_sparse[tid] = 0.0f;      // warp 0 zeroes before named bar

        int   mymeta = 0x7FFFFFFF;
        float mytx = 0.f, myty = 0.f, mytw = 0.f, myth = 0.f;
        if (tid < NT) {
            const float* t = tg + ((size_t)b * NT + tid) * 5;
            float t0 = t[0], t1 = t[1], t2 = t[2], t3 = t[3], t4 = t[4];
            if (t0 + t1 + t2 + t3 + t4 > 0.0f) {
                float gx = t0 * (float)WW, gy = t1 * (float)HH;
                float gw = t2 * (float)WW, gh = t3 * (float)HH;
                int gi = (int)gx, gj = (int)gy;
                const float aw[3] = {14.5f, 19.5f, 46.625f};   // ANCHORS / 8
                const float ah[3] = {11.25f, 24.75f, 40.75f};
                float area = (gw + 1.0f) * (gh + 1.0f);
                float best = -1.0f; int bn = 0, nz = 0;
                #pragma unroll
                for (int a = 0; a < 3; a++) {
                    float inter = fmaxf(fminf(gw, aw[a]) + 1.0f, 0.0f) *
                                  fmaxf(fminf(gh, ah[a]) + 1.0f, 0.0f);
                    float iou = inter / (area + (aw[a] + 1.0f) * (ah[a] + 1.0f) - inter + 1e-16f);
                    if (iou > best) { best = iou; bn = a; }      // first max wins
                    if (iou > 0.5f) nz |= (1 << a);
                }
                mytx = gx - (float)gi;
                myty = gy - (float)gj;
                mytw = __logf(gw / aw[bn] + 1e-16f);
                myth = __logf(gh / ah[bn] + 1e-16f);
                mymeta = (gj * WW + gi) | (bn << 14) | (nz << 16) | (((int)t4) << 19);
            }
            s_meta[tid] = mymeta;
        }

        // speculative in-range loads: box + conf + ALL class channels (one epoch)
        const bool inr = (mymeta != 0x7FFFFFFF) &&
                         ((mymeta & 0x3FFF) >= P0) && ((mymeta & 0x3FFF) < P0 + BLK_POS);
        float vx = 0, vy = 0, vw = 0, vh = 0, vc = 0, cfa0 = 0, cfa1 = 0, cfa2 = 0;
        float pc[NCLS];
        int   mypos = 0, mya = 0;
        if (inr) {
            mypos = mymeta & 0x3FFF;
            mya   = (mymeta >> 14) & 3;
            const float* ch = base + (size_t)(mya * 25) * HW + mypos;
            vx = ch[0]; vy = ch[HW]; vw = ch[2 * HW]; vh = ch[3 * HW]; vc = ch[4 * HW];
            #pragma unroll
            for (int c = 0; c < NCLS; c++) pc[c] = ch[(size_t)(5 + c) * HW];
            cfa0 = base[(size_t)( 4) * HW + mypos];
            cfa1 = base[(size_t)(29) * HW + mypos];
            cfa2 = base[(size_t)(54) * HW + mypos];
        }

        asm volatile("bar.sync 1, 64;" ::: "memory");   // warps 0-1 only

        if (inr) {
            int      mynz  = (mymeta >> 16) & 7;
            unsigned cm    = 1u << ((mymeta >> 19) & 31);
            bool     alive = true;
            int      subnz = mynz;
            for (int u = 0; u < NT; u++) {
                if (u == tid) continue;
                int mu = s_meta[u];
                if ((mu & 0x3FFF) != mypos) continue;            // sentinel never matches
                if (((mu >> 14) & 3) == mya) {
                    if (u > tid) alive = false;                  // last duplicate wins
                    else         cm |= 1u << ((mu >> 19) & 31);  // union earlier classes
                }
                if (u < tid) subnz &= ~((mu >> 16) & 7);         // earliest owner subtracts
            }
            float sub = 0.0f;            // remove ignored cells from dense sum
            if (subnz & 1) sub += spl(cfa0);
            if (subnz & 2) sub += spl(cfa1);
            if (subnz & 4) sub += spl(cfa2);
            if (sub != 0.0f) atomicAdd(&s_sparse[5], -sub);

            if (alive) {
                float scl = 0.0f;
                #pragma unroll
                for (int c = 0; c < NCLS; c++)
                    scl += spl(((cm >> c) & 1) ? -pc[c] : pc[c]);
                // BCE(sigm(z), t) = t*spl(-z) + (1-t)*spl(z)
                atomicAdd(&s_sparse[0], mytx * spl(-vx) + (1.0f - mytx) * spl(vx));
                atomicAdd(&s_sparse[1], myty * spl(-vy) + (1.0f - myty) * spl(vy));
                float dw = vw - mytw, dh = vh - myth;
                atomicAdd(&s_sparse[2], dw * dw);
                atomicAdd(&s_sparse[3], dh * dh);
                atomicAdd(&s_sparse[4], spl(-vc));
                atomicAdd(&s_sparse[6], scl);
                atomicAdd(&s_sparse[7], 1.0f);
            }
        }
    }

    // ---- 3. dense math (all warps; independent of targets) ----
    float a_no = 0.0f;
    if (live)
        a_no = spl(c0.x) + spl(c0.y) + spl(c1.x) + spl(c1.y) + spl(c2.x) + spl(c2.y);
    #pragma unroll
    for (int off = 16; off > 0; off >>= 1)
        a_no += __shfl_down_sync(0xFFFFFFFFu, a_no, off);
    if (lane == 0) s_no[wrp] = a_no;    // plain store, own slot

    __syncthreads();                    // the ONLY full-block barrier

    // ---- 4. one global accumulation per block ----
    if (tid < 8) {
        float p = s_sparse[tid];
        if (tid == 5) {
            #pragma unroll
            for (int w8 = 0; w8 < 8; w8++) p += s_no[w8];
        }
        if (p != 0.0f) atomicAdd(&g_acc[tid], (double)p);
    }
    __threadfence();
    __syncthreads();
    if (tid == 0) s_last = (atomicAdd(&g_ctr, 1) == NBLK - 1);
    __syncthreads();

    // ---- 5. last block finalizes + resets ----
    if (s_last && tid == 0) {
        __threadfence();
        double A[8];
        #pragma unroll
        for (int i = 0; i < 8; i++) A[i] = atomicAdd(&g_acc[i], 0.0);  // coherent read
        out[0] = (float)(2.5 * A[0] / NCELL);
        out[1] = (float)(2.5 * A[1] / NCELL);
        out[2] = (float)(2.5 * A[2] / NCELL);
        out[3] = (float)(2.5 * A[3] / NCELL);
        out[4] = (float)((A[4] + 0.5 * A[5]) / NCELL);
        out[5] = (float)(A[6] / fmax(A[7] * 20.0, 1.0));
        #pragma unroll
        for (int i = 0; i < 8; i++) g_acc[i] = 0.0;          // reset for next replay
        __threadfence();
        g_ctr = 0;
    }
}

extern "C" void kernel_launch(void* const* d_in, const int* in_sizes, int n_in,
                              void* d_out, int out_size) {
    const float* in = (const float*)d_in[0];   // (32,75,104,104)
    const float* tg = (const float*)d_in[1];   // (32,50,5)
    float* out = (float*)d_out;                // 6 floats

    dim3 grid(NBX, BSZ);                       // (22, 32) = 704 blocks
    yolo_fused<<<grid, 256>>>(in, tg, out);
}